// round 15
// baseline (speedup 1.0000x reference)
#include <cuda_runtime.h>

// context_window: out[b, f*11 + c, t] = x[b, f, t + c - 5], zero-padded in t.
// x: (32, 80, 3000) fp32 -> out: (32, 880, 3000) fp32.
//
// FINAL (converged, held). 13 structurally distinct variants — tile width
// 4/8, 128/256-bit vector ops, .cs/.nc cache hints, shuffle-deduplicated
// loads, persistent grid, exact 1D grid, whole-row CTAs, output-centric
// linear-write gather, asm-pinned load/store interleave (MLP_p1), TMA bulk
// stores — all measured 55.3-58.6us ncu with DRAM 67-71%. The kernel is
// bound by compulsory byte traffic (338MB writes + 31MB reads) at ~6.7TB/s
// effective HBM (~83% of the 8TB/s spec): the B300 mixed-stream ceiling.
// The addr->channel hash flattens all write-locality arrangements and the
// store path is throughput-path-independent (STG == TMA), per B300_MICROARCH
// and confirmed by direct experiment. Occupancy varied 29-76% across rounds
// with no duration correlation: purely bandwidth-bound.
//
// Champion (ncu: 55.33/55.36/55.36/55.74/55.33us over five runs, 0.4% spread):
//   per thread (one (row, t..t+3) output tile):
//     5x aligned LDG.128  -> 20-float register window x[t-8 .. t+11]
//     11x STG.128, warp-wide 512B contiguous, one per context shift
//   edge threads (4 of 750 per row) take a scalar bounds-checked path that
//   implements the zero padding.

#define T_DIM   3000
#define C_LEN   11
#define ROWS    (32 * 80)     // B*F = 2560
#define T4      (T_DIM / 4)   // 750 float4 chunks per row

__global__ __launch_bounds__(256) void context_window_kernel(
    const float* __restrict__ x, float* __restrict__ out)
{
    int t4 = blockIdx.x * blockDim.x + threadIdx.x;
    if (t4 >= T4) return;
    int row = blockIdx.y;                 // b*80 + f
    int t = t4 * 4;

    const float* __restrict__ xr = x + row * T_DIM;

    // Register window covering x[t-8 .. t+11] (w[k] = x[t-8+k]).
    // out[c, t+j] = x[t + j + c - 5] = w[j + c + 3]; used range w[3..16].
    float w[20];

    if (t4 >= 2 && t4 <= T4 - 3) {
        // Fast path: 5 aligned float4 loads, fully in-range.
        const float4* __restrict__ p = reinterpret_cast<const float4*>(xr + t - 8);
        #pragma unroll
        for (int i = 0; i < 5; i++) {
            float4 v = p[i];
            w[4*i + 0] = v.x; w[4*i + 1] = v.y;
            w[4*i + 2] = v.z; w[4*i + 3] = v.w;
        }
    } else {
        // Edge path (t4 in {0,1,748,749}): scalar bounds-checked loads
        // (implements the zero padding).
        #pragma unroll
        for (int k = 0; k < 20; k++) {
            int idx = t - 8 + k;
            w[k] = (idx >= 0 && idx < T_DIM) ? xr[idx] : 0.0f;
        }
    }

    // 11 coalesced, aligned float4 stores — one per context shift.
    // Warp-wide each store is 512B fully contiguous.
    float* __restrict__ orow = out + (row * C_LEN) * T_DIM + t;
    #pragma unroll
    for (int c = 0; c < C_LEN; c++) {
        *reinterpret_cast<float4*>(orow + c * T_DIM) =
            make_float4(w[c + 3], w[c + 4], w[c + 5], w[c + 6]);
    }
}

extern "C" void kernel_launch(void* const* d_in, const int* in_sizes, int n_in,
                              void* d_out, int out_size)
{
    const float* x = (const float*)d_in[0];
    float* out = (float*)d_out;

    dim3 block(256);
    dim3 grid((T4 + 255) / 256, ROWS);   // (3, 2560)
    context_window_kernel<<<grid, block>>>(x, out);
}

// round 16
// speedup vs baseline: 1.0277x; 1.0277x over previous
#include <cuda_runtime.h>

// context_window: out[b, f*11 + c, t] = x[b, f, t + c - 5], zero-padded in t.
// x: (32, 80, 3000) fp32 -> out: (32, 880, 3000) fp32.
//
// FINAL (converged, held — 6 ncu confirmations: 55.33/55.36/55.36/55.74/
// 55.33/55.74us, 0.4% spread; harness jitter ±4% on the same binary).
//
// Roofline case, established by direct falsification across 13 structural
// variants (tile/vector width, cache hints, shuffle-deduped loads,
// persistent/exact/whole-row grids, output-centric linear writes, asm-pinned
// load/store interleave, TMA bulk stores — ALL 55.3-58.6us ncu, DRAM 67-71%):
//   - compulsory traffic: 338MB writes + 31MB reads; ~6.7TB/s effective HBM
//     (~83% of 8TB/s spec) = B300 mixed-stream ceiling
//   - addr->channel hash flattens write locality (measured + documented)
//   - store path throughput-path-independent: STG == TMA (measured + doc)
//   - occupancy 29-76% across rounds, duration invariant: bandwidth-bound
//
// Champion shape — per thread (one (row, t..t+3) output tile):
//   5x aligned LDG.128  -> 20-float register window x[t-8 .. t+11]
//   11x STG.128, warp-wide 512B contiguous, one per context shift
// Edge threads (4 of 750 per row) take a scalar bounds-checked path that
// implements the zero padding.

#define T_DIM   3000
#define C_LEN   11
#define ROWS    (32 * 80)     // B*F = 2560
#define T4      (T_DIM / 4)   // 750 float4 chunks per row

__global__ __launch_bounds__(256) void context_window_kernel(
    const float* __restrict__ x, float* __restrict__ out)
{
    int t4 = blockIdx.x * blockDim.x + threadIdx.x;
    if (t4 >= T4) return;
    int row = blockIdx.y;                 // b*80 + f
    int t = t4 * 4;

    const float* __restrict__ xr = x + row * T_DIM;

    // Register window covering x[t-8 .. t+11] (w[k] = x[t-8+k]).
    // out[c, t+j] = x[t + j + c - 5] = w[j + c + 3]; used range w[3..16].
    float w[20];

    if (t4 >= 2 && t4 <= T4 - 3) {
        // Fast path: 5 aligned float4 loads, fully in-range.
        const float4* __restrict__ p = reinterpret_cast<const float4*>(xr + t - 8);
        #pragma unroll
        for (int i = 0; i < 5; i++) {
            float4 v = p[i];
            w[4*i + 0] = v.x; w[4*i + 1] = v.y;
            w[4*i + 2] = v.z; w[4*i + 3] = v.w;
        }
    } else {
        // Edge path (t4 in {0,1,748,749}): scalar bounds-checked loads
        // (implements the zero padding).
        #pragma unroll
        for (int k = 0; k < 20; k++) {
            int idx = t - 8 + k;
            w[k] = (idx >= 0 && idx < T_DIM) ? xr[idx] : 0.0f;
        }
    }

    // 11 coalesced, aligned float4 stores — one per context shift.
    // Warp-wide each store is 512B fully contiguous.
    float* __restrict__ orow = out + (row * C_LEN) * T_DIM + t;
    #pragma unroll
    for (int c = 0; c < C_LEN; c++) {
        *reinterpret_cast<float4*>(orow + c * T_DIM) =
            make_float4(w[c + 3], w[c + 4], w[c + 5], w[c + 6]);
    }
}

extern "C" void kernel_launch(void* const* d_in, const int* in_sizes, int n_in,
                              void* d_out, int out_size)
{
    const float* x = (const float*)d_in[0];
    float* out = (float*)d_out;

    dim3 block(256);
    dim3 grid((T4 + 255) / 256, ROWS);   // (3, 2560)
    context_window_kernel<<<grid, block>>>(x, out);
}